// round 15
// baseline (speedup 1.0000x reference)
#include <cuda_runtime.h>
#include <math.h>

#define EN 131072
#define NN 8192
#define NK 8192
#define WFULL 0xffffffffu

__device__ float4 g_y4[EN];
__device__ float2 g_rl[EN];
__device__ float4 g_ey4[EN];
__device__ float2 g_erl[EN];
__device__ float  g_state[NN * 256];
__device__ float  g_state2[NN * 256];
__device__ float  g_Abuf[NN * 256];
__device__ float  g_Bbuf[NN * 256];
__device__ float2 g_tab2[(size_t)3 * NK * 320];
__device__ float2 g_tabf2[NK * 64];
__device__ int    g_deg[NN];
__device__ int    g_cursor[NN];
__device__ int    g_rowstart[NN + 1];
__device__ int    g_csrc[EN];

#define IS32 0.17677669529663687f
#define IS10 0.31622776601683794f
#define IV2  0.7071067811865476f
#define IV3  0.5773502691896258f
#define CSC  0.3826834323650898f
#define CXC  0.9238795325112867f
#define CS32 (CSC * IS32)
#define CX8  (CXC * 0.125f)
#define CX96 (CXC * 0.10206207261596575f)
#define EMBSC 2.8234622306428f
#define OUTSC 0.044194173824159216f
#define RDELTA (8.0f / 8191.0f)
#define RINV   (8191.0f / 8.0f)

// table builder: 32 knots per block (computes 33 for deltas), ncol outputs/knot
__device__ __forceinline__ void dev_table2(
    const float* __restrict__ rw1, const float* __restrict__ rw2,
    float2* __restrict__ tab2, int ncol, int knot0, float* sbuf) {
    float* em   = sbuf;            // 330
    float* h    = sbuf + 330;      // 3300
    float* vals = sbuf + 3630;     // 33*ncol
    int t = threadIdx.x;
    for (int i = t; i < 330; i += 256) {
        int k = i / 10, j = i - k * 10;
        float r = (float)(knot0 + k) * RDELTA;
        float d = (r - (float)j * (4.0f/9.0f)) * 2.25f;
        em[i] = expf(-d*d) * EMBSC;
    }
    __syncthreads();
    for (int i = t; i < 3300; i += 256) {
        int k = i / 100, j = i - k * 100;
        float s = 0.0f;
#pragma unroll
        for (int m = 0; m < 10; m++) s += em[k*10+m] * rw1[m*100+j];
        s *= IS10;
        h[i] = s / (1.0f + __expf(-s));
    }
    __syncthreads();
    int total33 = 33 * ncol;
    for (int i = t; i < total33; i += 256) {
        int k = i / ncol, col = i - k * ncol;
        float acc = 0.0f;
#pragma unroll 4
        for (int m = 0; m < 100; m++) acc += h[k*100+m] * rw2[m*ncol+col];
        vals[i] = acc * 0.1f;
    }
    __syncthreads();
    int total = 32 * ncol;
    for (int i = t; i < total; i += 256) {
        int k = i / ncol, col = i - k * ncol;
        float v0 = vals[k*ncol + col], v1 = vals[(k+1)*ncol + col];
        tab2[(size_t)(knot0 + k) * ncol + col] = make_float2(v0, v1 - v0);
    }
}

// ===== k_setup: geom+hist (b<512) | lin1 layer0 (512..1535) | tables (1536..2559)
__global__ void __launch_bounds__(256) k_setup(
    const float* __restrict__ x, const float* __restrict__ ev,
    const int* __restrict__ dst,
    const float* __restrict__ w1so, const float* __restrict__ w1se,
    const float* __restrict__ w1vo, const float* __restrict__ w1ve,
    const float* __restrict__ rw1, const float* __restrict__ rw2,
    const float* __restrict__ frw1, const float* __restrict__ frw2) {
    extern __shared__ float sbuf[];
    int b = blockIdx.x, t = threadIdx.x;
    if (b < 512) {
        int e = b * 256 + t;
        float vx = ev[e*3], vy = ev[e*3+1], vz = ev[e*3+2];
        float r = sqrtf(vx*vx + vy*vy + vz*vz);
        float inv = 1.0f / (r + 1e-12f);
        float uu = 0.5f * r - 2.0f;
        float cut;
        if (uu > 0.0f) cut = 0.0f;
        else if (uu < -1.0f) cut = 1.0f;
        else cut = 0.5f * (1.0f - cosf(3.14159265358979323846f * uu));
        const float SQ3 = 1.7320508075688772f;
        float s = SQ3 * inv * cut;
        g_y4[e] = make_float4(cut, s*vx, s*vy, s*vz);
        float xq = r * RINV;
        int ri = (int)xq;
        if (ri > NK - 2) ri = NK - 2;
        float rf = xq - (float)ri;
        if (rf > 1.0f) rf = 1.0f;
        g_rl[e] = make_float2((float)ri, rf);
        atomicAdd(&g_deg[dst[e]], 1);
        return;
    }
    if (b >= 1536) {
        int tb = b - 1536;
        if (tb < 768) {
            int layer = tb >> 8, kg = tb & 255;
            dev_table2(rw1 + layer*1000, rw2 + layer*32000,
                       g_tab2 + (size_t)layer*NK*320, 320, kg*32, sbuf);
        } else {
            int kg = tb - 768;
            dev_table2(frw1, frw2, g_tabf2, 64, kg*32, sbuf);
        }
        return;
    }
    // lin1 layer 0 -> g_Abuf in [n][u][8] layout
    float* ws = sbuf;
    for (int i = t; i < 1024; i += 256) {
        ws[i] = w1so[i]; ws[1024+i] = w1se[i]; ws[2048+i] = w1vo[i]; ws[3072+i] = w1ve[i];
    }
    __syncthreads();
    int u = t & 31, wp = t >> 5;
    int n = (b - 512) * 8 + wp;
    const float* s = x + n * 256;
    float so = s[u], se = s[32+u];
    float vo0 = s[64+u*3], vo1 = s[64+u*3+1], vo2 = s[64+u*3+2];
    float ve0 = s[160+u*3], ve1 = s[160+u*3+1], ve2 = s[160+u*3+2];
    float aso=0, ase=0, avo0=0, avo1=0, avo2=0, ave0=0, ave1=0, ave2=0;
#pragma unroll
    for (int v = 0; v < 32; v++) {
        float a = __shfl_sync(WFULL, so, v), bb = __shfl_sync(WFULL, se, v);
        float c0 = __shfl_sync(WFULL, vo0, v), c1 = __shfl_sync(WFULL, vo1, v), c2 = __shfl_sync(WFULL, vo2, v);
        float d0 = __shfl_sync(WFULL, ve0, v), d1 = __shfl_sync(WFULL, ve1, v), d2 = __shfl_sync(WFULL, ve2, v);
        float w0 = ws[v*32+u], w1 = ws[1024+v*32+u], w2 = ws[2048+v*32+u], w3 = ws[3072+v*32+u];
        aso += a*w0; ase += bb*w1;
        avo0 += c0*w2; avo1 += c1*w2; avo2 += c2*w2;
        ave0 += d0*w3; ave1 += d1*w3; ave2 += d2*w3;
    }
    float* A = g_Abuf + n * 256 + u * 8;
    *(float4*)(A)     = make_float4(aso*IS32, ase*IS32, avo0*IS32, avo1*IS32);
    *(float4*)(A + 4) = make_float4(avo2*IS32, ave0*IS32, ave1*IS32, ave2*IS32);
}

__global__ void k_scan(float* __restrict__ out) {
    __shared__ int part[1024];
    int t = threadIdx.x;
    if (t < 16) out[t] = 0.0f;
    int loc[8]; int run = 0;
#pragma unroll
    for (int i = 0; i < 8; i++) { loc[i] = run; run += g_deg[t*8+i]; }
    part[t] = run;
    __syncthreads();
    for (int off = 1; off < 1024; off <<= 1) {
        int xv = (t >= off) ? part[t-off] : 0;
        __syncthreads();
        part[t] += xv;
        __syncthreads();
    }
    int base = (t > 0) ? part[t-1] : 0;
#pragma unroll
    for (int i = 0; i < 8; i++) g_rowstart[t*8+i] = base + loc[i];
    if (t == 1023) g_rowstart[NN] = EN;
}

__global__ void k_scatter(const int* __restrict__ dst, const int* __restrict__ src) {
    int e = blockIdx.x * blockDim.x + threadIdx.x;
    if (e >= EN) return;
    int d = dst[e];
    int pos = atomicAdd(&g_cursor[d], 1);
    int slot = g_rowstart[d] + pos;
    g_csrc[slot] = src[e];
    g_ey4[slot] = g_y4[e];
    g_erl[slot] = g_rl[e];
}

// dst-centric messages + fused node update + fused next-layer lin1 epilogue.
// 512 threads = 16 warps = 16 nodes/block.
// mode 0: epilogue = lin1 (4 weight mats) -> Aout [n][u][8]
// mode 1: epilogue = final-head lin1 (2 mats) -> Aout [n][u][4]
__global__ void __launch_bounds__(512, 2) k_msg(
    const float* __restrict__ wsso, const float* __restrict__ wsse,
    const float* __restrict__ wsvo, const float* __restrict__ wsve,
    const float* __restrict__ w2so, const float* __restrict__ w2se,
    const float* __restrict__ w2vo, const float* __restrict__ w2ve,
    const float* __restrict__ stin_base, float* __restrict__ stout_base,
    const float* __restrict__ Ain, float* __restrict__ Aout,
    const float2* __restrict__ tab2,
    const float* __restrict__ wn0, const float* __restrict__ wn1,
    const float* __restrict__ wn2, const float* __restrict__ wn3,
    int mode) {
    extern __shared__ float sm[];
    float* s_wsso = sm;
    float* s_wsse = sm + 1024;
    float* s_wsvo = sm + 4096;
    float* s_wsve = sm + 5120;
    float* s_w2so = sm + 6144;
    float* s_w2se = sm + 8192;
    float* s_w2vo = sm + 14336;
    float* s_w2ve = sm + 17408;
    float* W      = sm + 20480;
    int t = threadIdx.x;
    for (int i = t; i < 1024; i += 512) { s_wsso[i]=wsso[i]; s_wsvo[i]=wsvo[i]; s_wsve[i]=wsve[i]; }
    for (int i = t; i < 3072; i += 512) { s_wsse[i]=wsse[i]; s_w2vo[i]=w2vo[i]; s_w2ve[i]=w2ve[i]; }
    for (int i = t; i < 2048; i += 512) s_w2so[i]=w2so[i];
    for (int i = t; i < 6144; i += 512) s_w2se[i]=w2se[i];
    if (mode == 0) {
        for (int i = t; i < 1024; i += 512) {
            W[i]=wn0[i]; W[1024+i]=wn1[i]; W[2048+i]=wn2[i]; W[3072+i]=wn3[i];
        }
    } else {
        for (int i = t; i < 1024; i += 512) { W[i]=wn0[i]; W[1024+i]=wn1[i]; }
    }
    __syncthreads();
    int u = t & 31, wp = t >> 5;
    int n = blockIdx.x * 16 + wp;
    const float* stin = stin_base + n * 256;
    float* stout = stout_base + n * 256;

    float n0oa=0, n0ob=0, n0ea=0, n0eb=0;
    float p00=0,p01=0,p02=0,p10=0,p11=0,p12=0,p20=0,p21=0,p22=0;
    float q00=0,q01=0,q02=0,q10=0,q11=0,q12=0,q20=0,q21=0,q22=0;

    int beg = g_rowstart[n], end = g_rowstart[n+1];
    int srcn = (beg < end) ? g_csrc[beg] : 0;
    for (int idx = beg; idx < end; idx++) {
        int src = srcn;
        if (idx + 1 < end) srcn = g_csrc[idx + 1];
        float4 y = g_ey4[idx];
        float2 rlv = g_erl[idx];
        int ri = (int)rlv.x;
        float rf = rlv.y;
        float y0 = y.x, y10 = y.y, y11 = y.z, y12 = y.w;
        const float* a = Ain + src * 256 + u * 8;
        float4 A0 = *(const float4*)(a);
        float4 A1 = *(const float4*)(a + 4);
        float eso = A0.x, ese = A0.y;
        float evo0 = A0.z, evo1 = A0.w, evo2 = A1.x;
        float eve0 = A1.y, eve1 = A1.z, eve2 = A1.w;
        const float2* ta = tab2 + (size_t)ri * 320 + u;
        float2 x0 = ta[0],   x1 = ta[32],  x2 = ta[64],  x3 = ta[96],  x4 = ta[128];
        float2 x5 = ta[160], x6 = ta[192], x7 = ta[224], x8 = ta[256], x9 = ta[288];
        float w0 = x0.x + rf*x0.y, w1 = x1.x + rf*x1.y, w2 = x2.x + rf*x2.y;
        float w3 = x3.x + rf*x3.y, w4 = x4.x + rf*x4.y, w5 = x5.x + rf*x5.y;
        float w6 = x6.x + rf*x6.y, w7 = x7.x + rf*x7.y, w8 = x8.x + rf*x8.y;
        float w9 = x9.x + rf*x9.y;
        float dve = (eve0*y10 + eve1*y11 + eve2*y12) * IV3;
        float dvo = (evo0*y10 + evo1*y11 + evo2*y12) * IV3;
        float cve0 = (eve1*y12 - eve2*y11) * IV2;
        float cve1 = (eve2*y10 - eve0*y12) * IV2;
        float cve2 = (eve0*y11 - eve1*y10) * IV2;
        float cvo0 = (evo1*y12 - evo2*y11) * IV2;
        float cvo1 = (evo2*y10 - evo0*y12) * IV2;
        float cvo2 = (evo0*y11 - evo1*y10) * IV2;
        n0oa += w0 * (eso * y0);  n0ob += w1 * dve;
        n0ea += w2 * (ese * y0);  n0eb += w3 * dvo;
        float sy = w4 * ese;
        p00 += sy*y10; p01 += sy*y11; p02 += sy*y12;
        float py = w5 * y0;
        p10 += py*evo0; p11 += py*evo1; p12 += py*evo2;
        p20 += w6*cve0; p21 += w6*cve1; p22 += w6*cve2;
        float qy = w7 * eso;
        q00 += qy*y10; q01 += qy*y11; q02 += qy*y12;
        q10 += w8*cvo0; q11 += w8*cvo1; q12 += w8*cvo2;
        float ry = w9 * y0;
        q20 += ry*eve0; q21 += ry*eve1; q22 += ry*eve2;
    }
    const float S0 = IV2 * 0.25f * CX8;
    const float S1 = IV3 * 0.25f * CX96;
    n0oa*=S0; n0ob*=S0; n0ea*=S0; n0eb*=S0;
    p00*=S1;p01*=S1;p02*=S1;p10*=S1;p11*=S1;p12*=S1;p20*=S1;p21*=S1;p22*=S1;
    q00*=S1;q01*=S1;q02*=S1;q10*=S1;q11*=S1;q12*=S1;q20*=S1;q21*=S1;q22*=S1;
    float so = stin[u]*CS32, se = stin[32+u]*CS32;
    float vo0 = stin[64+u*3]*CS32, vo1 = stin[64+u*3+1]*CS32, vo2 = stin[64+u*3+2]*CS32;
    float ve0 = stin[160+u*3]*CS32, ve1 = stin[160+u*3+1]*CS32, ve2 = stin[160+u*3+2]*CS32;

    float o0o=0, oe0=0, oe1=0, oe2=0;
    float t00=0,t01=0,t02=0,t10=0,t11=0,t12=0;
#pragma unroll 4
    for (int v = 0; v < 32; v++) {
        float sov = __shfl_sync(WFULL, so, v), sev = __shfl_sync(WFULL, se, v);
        float a0 = __shfl_sync(WFULL, n0oa, v), b0 = __shfl_sync(WFULL, n0ob, v);
        float a1 = __shfl_sync(WFULL, n0ea, v), b1 = __shfl_sync(WFULL, n0eb, v);
        float vo0v = __shfl_sync(WFULL, vo0, v), vo1v = __shfl_sync(WFULL, vo1, v), vo2v = __shfl_sync(WFULL, vo2, v);
        float ve0v = __shfl_sync(WFULL, ve0, v), ve1v = __shfl_sync(WFULL, ve1, v), ve2v = __shfl_sync(WFULL, ve2, v);
        float P00=__shfl_sync(WFULL,p00,v), P01=__shfl_sync(WFULL,p01,v), P02=__shfl_sync(WFULL,p02,v);
        float P10=__shfl_sync(WFULL,p10,v), P11=__shfl_sync(WFULL,p11,v), P12=__shfl_sync(WFULL,p12,v);
        float P20=__shfl_sync(WFULL,p20,v), P21=__shfl_sync(WFULL,p21,v), P22=__shfl_sync(WFULL,p22,v);
        float Q00=__shfl_sync(WFULL,q00,v), Q01=__shfl_sync(WFULL,q01,v), Q02=__shfl_sync(WFULL,q02,v);
        float Q10=__shfl_sync(WFULL,q10,v), Q11=__shfl_sync(WFULL,q11,v), Q12=__shfl_sync(WFULL,q12,v);
        float Q20=__shfl_sync(WFULL,q20,v), Q21=__shfl_sync(WFULL,q21,v), Q22=__shfl_sync(WFULL,q22,v);

        float wa = s_wsso[v*32+u];
        float m0 = s_w2so[v*32+u], m1 = s_w2so[(32+v)*32+u];
        o0o += sov*wa + a0*m0 + b0*m1;

        float wb0 = s_wsse[v*96+u], wb1 = s_wsse[v*96+32+u], wb2 = s_wsse[v*96+64+u];
        float n0 = s_w2se[v*96+u], n1 = s_w2se[v*96+32+u], n2 = s_w2se[v*96+64+u];
        float n3 = s_w2se[(32+v)*96+u], n4 = s_w2se[(32+v)*96+32+u], n5 = s_w2se[(32+v)*96+64+u];
        oe0 += sev*wb0 + a1*n0 + b1*n3;
        oe1 += sev*wb1 + a1*n1 + b1*n4;
        oe2 += sev*wb2 + a1*n2 + b1*n5;

        float wc = s_wsvo[v*32+u];
        float r0 = s_w2vo[v*32+u], r1 = s_w2vo[(32+v)*32+u], r2 = s_w2vo[(64+v)*32+u];
        t00 += vo0v*wc + P00*r0 + P10*r1 + P20*r2;
        t01 += vo1v*wc + P01*r0 + P11*r1 + P21*r2;
        t02 += vo2v*wc + P02*r0 + P12*r1 + P22*r2;

        float wd = s_wsve[v*32+u];
        float z0 = s_w2ve[v*32+u], z1 = s_w2ve[(32+v)*32+u], z2 = s_w2ve[(64+v)*32+u];
        t10 += ve0v*wd + Q00*z0 + Q10*z1 + Q20*z2;
        t11 += ve1v*wd + Q01*z0 + Q11*z1 + Q21*z2;
        t12 += ve2v*wd + Q02*z0 + Q12*z1 + Q22*z2;
    }
    float nso = tanhf(o0o);
    float nse = oe0 / (1.0f + __expf(-oe0));
    float g1 = 1.0f / (1.0f + __expf(-oe1));
    float g2 = 1.0f / (1.0f + __expf(-oe2));
    float gv0 = t00*g1, gv1 = t01*g1, gv2 = t02*g1;
    float gw0 = t10*g2, gw1 = t11*g2, gw2 = t12*g2;
    stout[u] = nso; stout[32+u] = nse;
    stout[64+u*3] = gv0; stout[64+u*3+1] = gv1; stout[64+u*3+2] = gv2;
    stout[160+u*3] = gw0; stout[160+u*3+1] = gw1; stout[160+u*3+2] = gw2;

    // fused next-layer lin1 epilogue
    if (mode == 0) {
        float aso=0, asE=0, avo0=0, avo1=0, avo2=0, ave0=0, ave1=0, ave2=0;
#pragma unroll 4
        for (int v = 0; v < 32; v++) {
            float a = __shfl_sync(WFULL, nso, v), b = __shfl_sync(WFULL, nse, v);
            float c0 = __shfl_sync(WFULL, gv0, v), c1 = __shfl_sync(WFULL, gv1, v), c2 = __shfl_sync(WFULL, gv2, v);
            float d0 = __shfl_sync(WFULL, gw0, v), d1 = __shfl_sync(WFULL, gw1, v), d2 = __shfl_sync(WFULL, gw2, v);
            float w0 = W[v*32+u], w1 = W[1024+v*32+u], w2 = W[2048+v*32+u], w3 = W[3072+v*32+u];
            aso += a*w0; asE += b*w1;
            avo0 += c0*w2; avo1 += c1*w2; avo2 += c2*w2;
            ave0 += d0*w3; ave1 += d1*w3; ave2 += d2*w3;
        }
        float* A = Aout + n * 256 + u * 8;
        *(float4*)(A)     = make_float4(aso*IS32, asE*IS32, avo0*IS32, avo1*IS32);
        *(float4*)(A + 4) = make_float4(avo2*IS32, ave0*IS32, ave1*IS32, ave2*IS32);
    } else {
        float asE=0, av0=0, av1=0, av2=0;
#pragma unroll 4
        for (int v = 0; v < 32; v++) {
            float b = __shfl_sync(WFULL, nse, v);
            float c0 = __shfl_sync(WFULL, gv0, v), c1 = __shfl_sync(WFULL, gv1, v), c2 = __shfl_sync(WFULL, gv2, v);
            float w0 = W[v*32+u], w1 = W[1024+v*32+u];
            asE += b*w0; av0 += c0*w1; av1 += c1*w1; av2 += c2*w1;
        }
        *(float4*)(Aout + n * 128 + u * 4) =
            make_float4(asE*IS32, av0*IS32, av1*IS32, av2*IS32);
    }
}

__global__ void __launch_bounds__(256) k_final(
    const int* __restrict__ batch,
    const float* __restrict__ fsc, const float* __restrict__ fl2,
    float* __restrict__ out) {
    int b = blockIdx.x, t = threadIdx.x, u = t & 31, wp = t >> 5;
    if (b < 32) g_deg[b*256 + t] = 0;
    else if (b < 64) g_cursor[(b-32)*256 + t] = 0;
    int n = b * 8 + wp;
    float na = 0, nb = 0;
    int beg = g_rowstart[n], end = g_rowstart[n+1];
    for (int idx = beg; idx < end; idx++) {
        int src = g_csrc[idx];
        float4 y = g_ey4[idx];
        float2 rlv = g_erl[idx];
        int ri = (int)rlv.x;
        float rf = rlv.y;
        float4 a = *(const float4*)(g_Bbuf + src * 128 + u * 4);
        const float2* ta = g_tabf2 + (size_t)ri * 64 + u;
        float2 x0 = ta[0], x1 = ta[32];
        float w0 = x0.x + rf*x0.y, w1 = x1.x + rf*x1.y;
        float dvo = (a.y*y.y + a.z*y.z + a.w*y.w) * IV3;
        na += w0 * (a.x * y.x);
        nb += w1 * dvo;
    }
    const float S = IV2 * 0.25f;
    na *= S; nb *= S;
    float se = g_state2[n*256 + 32 + u];
    float val = CS32 * se * fsc[u] + CX8 * (na * fl2[u] + nb * fl2[32+u]);
#pragma unroll
    for (int off = 16; off > 0; off >>= 1)
        val += __shfl_xor_sync(WFULL, val, off);
    if (u == 0) atomicAdd(&out[batch[n]], val * OUTSC);
}

extern "C" void kernel_launch(void* const* d_in, const int* in_sizes, int n_in,
                              void* d_out, int out_size) {
    const float* x        = (const float*)d_in[0];
    const float* edge_vec = (const float*)d_in[1];
    const float* lin1_so  = (const float*)d_in[2];
    const float* lin1_se  = (const float*)d_in[3];
    const float* lin1_vo  = (const float*)d_in[4];
    const float* lin1_ve  = (const float*)d_in[5];
    const float* sc_so    = (const float*)d_in[6];
    const float* sc_se    = (const float*)d_in[7];
    const float* sc_vo    = (const float*)d_in[8];
    const float* sc_ve    = (const float*)d_in[9];
    const float* rad_w1   = (const float*)d_in[10];
    const float* rad_w2   = (const float*)d_in[11];
    const float* lin2_so  = (const float*)d_in[12];
    const float* lin2_se  = (const float*)d_in[13];
    const float* lin2_vo  = (const float*)d_in[14];
    const float* lin2_ve  = (const float*)d_in[15];
    const float* flin1_se = (const float*)d_in[16];
    const float* flin1_vo = (const float*)d_in[17];
    const float* fsc_se   = (const float*)d_in[18];
    const float* frad_w1  = (const float*)d_in[19];
    const float* frad_w2  = (const float*)d_in[20];
    const float* flin2    = (const float*)d_in[21];
    const int*   edge_src = (const int*)d_in[22];
    const int*   edge_dst = (const int*)d_in[23];
    const int*   batch    = (const int*)d_in[24];
    float* out = (float*)d_out;

    const int SETUP_SMEM = 14190 * 4;   // 56,760 B
    const int MSG_SMEM   = 24576 * 4;   // 98,304 B
    cudaFuncSetAttribute(k_setup, cudaFuncAttributeMaxDynamicSharedMemorySize, SETUP_SMEM);
    cudaFuncSetAttribute(k_msg, cudaFuncAttributeMaxDynamicSharedMemorySize, MSG_SMEM);

    float* st2; cudaGetSymbolAddress((void**)&st2, g_state2);
    float* st1; cudaGetSymbolAddress((void**)&st1, g_state);
    float* bufA; cudaGetSymbolAddress((void**)&bufA, g_Abuf);
    float* bufB; cudaGetSymbolAddress((void**)&bufB, g_Bbuf);
    float2* tab2; cudaGetSymbolAddress((void**)&tab2, g_tab2);

    k_setup<<<2560, 256, SETUP_SMEM>>>(x, edge_vec, edge_dst,
                                       lin1_so, lin1_se, lin1_vo, lin1_ve,
                                       rad_w1, rad_w2, frad_w1, frad_w2);        // 1
    k_scan<<<1, 1024>>>(out);                                                    // 2
    k_scatter<<<512, 256>>>(edge_dst, edge_src);                                 // 3
    k_msg<<<512, 512, MSG_SMEM>>>(sc_so, sc_se, sc_vo, sc_ve,
                                  lin2_so, lin2_se, lin2_vo, lin2_ve,
                                  x, st2, bufA, bufB, tab2,
                                  lin1_so + 1024, lin1_se + 1024,
                                  lin1_vo + 1024, lin1_ve + 1024, 0);            // 4 (profiled)
    k_msg<<<512, 512, MSG_SMEM>>>(sc_so + 1024, sc_se + 3072, sc_vo + 1024, sc_ve + 1024,
                                  lin2_so + 2048, lin2_se + 6144,
                                  lin2_vo + 3072, lin2_ve + 3072,
                                  st2, st1, bufB, bufA, tab2 + (size_t)NK*320,
                                  lin1_so + 2048, lin1_se + 2048,
                                  lin1_vo + 2048, lin1_ve + 2048, 0);            // 5
    k_msg<<<512, 512, MSG_SMEM>>>(sc_so + 2048, sc_se + 6144, sc_vo + 2048, sc_ve + 2048,
                                  lin2_so + 4096, lin2_se + 12288,
                                  lin2_vo + 6144, lin2_ve + 6144,
                                  st1, st2, bufA, bufB, tab2 + (size_t)2*NK*320,
                                  flin1_se, flin1_vo, flin1_se, flin1_vo, 1);    // 6
    k_final<<<1024, 256>>>(batch, fsc_se, flin2, out);                           // 7
}